// round 15
// baseline (speedup 1.0000x reference)
#include <cuda_runtime.h>
#include <math.h>

#define EPSV 1e-4f

// scratch (device globals; allocation is banned)
__device__ __align__(16) float g_B[25165824];       // 12*512 matrices of 64x64
__device__ __align__(16) float g_Vt[25165824];      // eigenvectors, COLUMN-major V[col*64+row]
__device__ __align__(16) float g_w[393216];         // eigenvalues
__device__ __align__(16) float g_state[10485760];   // 5*512*4096
__device__ __align__(16) float g_Lstate[10485760];  // logm(states)

// ---------------- bimap: Y = W X W^T (64x64) --------------------------------
__device__ __forceinline__ void bimap64(const float* __restrict__ X,
                                        const float* __restrict__ W,
                                        float* __restrict__ Y,
                                        float* Ws, float* Xs) {
  const int t = threadIdx.x;
  for (int i = t; i < 4096; i += 256) {
    int r = i >> 6, c = i & 63;
    Ws[r * 65 + c] = W[i];
    Xs[r * 65 + c] = X[i];
  }
  __syncthreads();
  const int i0 = (t >> 4) * 4, j0 = (t & 15) * 4;
  float acc[4][4] = {};
  for (int k = 0; k < 64; k++) {          // T = W * X
    float a[4], b[4];
#pragma unroll
    for (int r = 0; r < 4; r++) a[r] = Ws[(i0 + r) * 65 + k];
#pragma unroll
    for (int c = 0; c < 4; c++) b[c] = Xs[k * 65 + j0 + c];
#pragma unroll
    for (int r = 0; r < 4; r++)
#pragma unroll
      for (int c = 0; c < 4; c++) acc[r][c] += a[r] * b[c];
  }
  __syncthreads();
#pragma unroll
  for (int r = 0; r < 4; r++)
#pragma unroll
    for (int c = 0; c < 4; c++) Xs[(i0 + r) * 65 + j0 + c] = acc[r][c];
  __syncthreads();
  float acc2[4][4] = {};
  for (int k = 0; k < 64; k++) {          // Y = T * W^T
    float a[4], b[4];
#pragma unroll
    for (int r = 0; r < 4; r++) a[r] = Xs[(i0 + r) * 65 + k];
#pragma unroll
    for (int c = 0; c < 4; c++) b[c] = Ws[(j0 + c) * 65 + k];
#pragma unroll
    for (int r = 0; r < 4; r++)
#pragma unroll
      for (int c = 0; c < 4; c++) acc2[r][c] += a[r] * b[c];
  }
#pragma unroll
  for (int r = 0; r < 4; r++)
#pragma unroll
    for (int c = 0; c < 4; c++) Y[(i0 + r) * 64 + j0 + c] = acc2[r][c];
}

__global__ void k_bimap_pre(const float* __restrict__ s0, const float* __restrict__ s1,
                            const float* __restrict__ Wp0, const float* __restrict__ Wp1) {
  __shared__ float Ws[4160], Xs[4160];
  int m = blockIdx.x, slot = m >> 9, bc = m & 511;
  const float* X = (slot ? s1 : s0) + (size_t)bc * 4096;
  const float* W = slot ? Wp1 : Wp0;
  bimap64(X, W, g_B + (size_t)m * 4096, Ws, Xs);
}

__global__ void k_bimap_step(const float* __restrict__ Wop, int o) {
  __shared__ float Ws[4160], Xs[4160];
  int m = blockIdx.x;
  int j = m / 1536, rem = m % 1536, r = rem / 512, k = r + 1, bc = rem % 512;
  const float* X = g_state + (size_t)(j * 512 + bc) * 4096;
  const float* W = Wop + (size_t)((o + j) * 4 + k) * 4096;
  bimap64(X, W, g_B + (size_t)m * 4096, Ws, Xs);
}

// ---------------- batched Jacobi eigh: adaptive skips + float2 V -------------
__global__ void __launch_bounds__(128, 8) k_eigh(int useL, int off) {
  __shared__ float As[4160];
  __shared__ __align__(16) float Vt[4096];   // column-major V[col*64+row]
  __shared__ float red[4];
  const int t = threadIdx.x;
  const int lane = t & 31, wid = t >> 5;   // wid 0..3
  const int m = blockIdx.x;
  const float* src = (useL ? g_Lstate : g_B) + (size_t)(off + m) * 4096;
  float2* V2 = reinterpret_cast<float2*>(Vt);

  float loc = 0.f;
  for (int i = t; i < 4096; i += 128) {
    int r = i >> 6, c = i & 63;
    float v = 0.5f * (src[i] + src[c * 64 + r]);
    As[r * 65 + c] = v;
    Vt[i] = (r == c) ? 1.f : 0.f;   // col-major identity (same diagonal set)
    loc += v * v;
  }
#pragma unroll
  for (int o2 = 16; o2; o2 >>= 1) loc += __shfl_xor_sync(~0u, loc, o2);
  if (lane == 0) red[wid] = loc;
  __syncthreads();
  const float thr = (red[0] + red[1] + red[2] + red[3]) * 1e-11f;

  for (int sweep = 0; sweep < 18; sweep++) {
    // convergence check: off-diagonal Frobenius^2 (all threads same decision)
    float l2 = 0.f;
    for (int i = t; i < 4096; i += 128) {
      int r = i >> 6, c = i & 63;
      float v = As[r * 65 + c];
      l2 += (r != c) ? v * v : 0.f;
    }
#pragma unroll
    for (int o2 = 16; o2; o2 >>= 1) l2 += __shfl_xor_sync(~0u, l2, o2);
    __syncthreads();                 // WAR guard (warps may drift in trivial rounds)
    if (lane == 0) red[wid] = l2;
    __syncthreads();
    const float sumoff = red[0] + red[1] + red[2] + red[3];
    if (sumoff <= thr) break;
    // adaptive per-pair trivial threshold: skipped mass <= 1% of current off^2
    const float skipthr = fmaxf(thr, sumoff * 0.01f) * (1.f / 2016.f);

    for (int mr = 1; mr < 64; mr++) {
      const int h = 31 - __clz(mr);
      const int msk = (1 << h) - 1;
      // phase a: every warp computes all 32 rotations (lane = pair index)
      const int pi = ((lane >> h) << (h + 1)) | (lane & msk);
      const int qi = pi ^ mr;
      float app = As[pi * 65 + pi];
      float aqq = As[qi * 65 + qi];
      float apq = As[pi * 65 + qi];
      float cc = 1.f, ss = 0.f;
      if (apq * apq > skipthr) {
        float tau = (aqq - app) / (2.f * apq);
        float tt = copysignf(1.f, tau) / (fabsf(tau) + sqrtf(1.f + tau * tau));
        cc = rsqrtf(1.f + tt * tt);
        ss = tt * cc;
      }
      // block-uniform triviality (every warp computes the identical set)
      if (__all_sync(~0u, ss == 0.f)) continue;  // no writes -> no barriers needed
      __syncthreads();  // rotation reads done before block writes

      // phase b: fused two-sided update. Thread (wid,lane) owns A blocks
      // (i=lane, j=wid+4k, k<8) and V rows {2*lane, 2*lane+1} for col-pairs j.
#pragma unroll
      for (int k = 0; k < 8; k++) {
        const int j = wid + 4 * k;
        const float cj = __shfl_sync(~0u, cc, j);
        const float sj = __shfl_sync(~0u, ss, j);
        const int tj = (sj == 0.f);                  // warp-uniform
        const int pj = ((j >> h) << (h + 1)) | (j & msk);
        const int qj = pj ^ mr;

        float b00 = As[pi * 65 + pj], b01 = As[pi * 65 + qj];
        float b10 = As[qi * 65 + pj], b11 = As[qi * 65 + qj];
        float t00 = cc * b00 - ss * b10, t01 = cc * b01 - ss * b11;
        float t10 = ss * b00 + cc * b10, t11 = ss * b01 + cc * b11;
        As[pi * 65 + pj] = t00 * cj - t01 * sj;
        As[pi * 65 + qj] = t00 * sj + t01 * cj;
        As[qi * 65 + pj] = t10 * cj - t11 * sj;
        As[qi * 65 + qj] = t10 * sj + t11 * cj;

        if (!tj) {
          float2 vp = V2[pj * 32 + lane], vq = V2[qj * 32 + lane];
          float2 np, nq;
          np.x = cj * vp.x - sj * vq.x;  np.y = cj * vp.y - sj * vq.y;
          nq.x = sj * vp.x + cj * vq.x;  nq.y = sj * vp.y + cj * vq.y;
          V2[pj * 32 + lane] = np;
          V2[qj * 32 + lane] = nq;
        }
      }
      __syncthreads();
    }
  }
  if (t < 64) g_w[(size_t)m * 64 + t] = As[t * 65 + t];
  for (int i = t; i < 4096; i += 128)
    g_Vt[(size_t)m * 4096 + i] = Vt[i];   // column-major out (coalesced both sides)
}

// transpose-on-load of column-major g_Vt into row-major pitch-65 smem
__device__ __forceinline__ void loadV(const float* __restrict__ V, float* Vs, int t) {
  for (int i = t; i < 4096; i += 256) Vs[(i & 63) * 65 + (i >> 6)] = V[i];
}

// ---------------- reconstructions V f(w) V^T --------------------------------
__global__ void k_recon_pre() {  // state = V clip(w) V^T ; Lstate = V log(clip(w)) V^T
  __shared__ float Vs[4160], fc[64], fl[64];
  const int m = blockIdx.x, t = threadIdx.x;
  const int slot = m >> 9, bc = m & 511;
  loadV(g_Vt + (size_t)m * 4096, Vs, t);
  if (t < 64) {
    float cw = fmaxf(g_w[(size_t)m * 64 + t], EPSV);
    fc[t] = cw; fl[t] = logf(cw);
  }
  __syncthreads();
  const int i0 = (t >> 4) * 4, j0 = (t & 15) * 4;
  float a[4][4] = {}, b[4][4] = {};
  for (int k = 0; k < 64; k++) {
    float u[4], v[4];
#pragma unroll
    for (int r = 0; r < 4; r++) u[r] = Vs[(i0 + r) * 65 + k];
#pragma unroll
    for (int c = 0; c < 4; c++) v[c] = Vs[(j0 + c) * 65 + k];
    float fck = fc[k], flk = fl[k];
#pragma unroll
    for (int r = 0; r < 4; r++)
#pragma unroll
      for (int c = 0; c < 4; c++) {
        float p = u[r] * v[c];
        a[r][c] += p * fck;
        b[r][c] += p * flk;
      }
  }
  float* st = g_state + (size_t)(slot * 512 + bc) * 4096;
  float* ls = g_Lstate + (size_t)(slot * 512 + bc) * 4096;
#pragma unroll
  for (int r = 0; r < 4; r++)
#pragma unroll
    for (int c = 0; c < 4; c++) {
      st[(i0 + r) * 64 + j0 + c] = a[r][c];
      ls[(i0 + r) * 64 + j0 + c] = b[r][c];
    }
}

__global__ void k_recon_log() {  // g_B[m] = V log(clip(w)) V^T
  __shared__ float Vs[4160], fl[64];
  const int m = blockIdx.x, t = threadIdx.x;
  loadV(g_Vt + (size_t)m * 4096, Vs, t);
  if (t < 64) fl[t] = logf(fmaxf(g_w[(size_t)m * 64 + t], EPSV));
  __syncthreads();
  const int i0 = (t >> 4) * 4, j0 = (t & 15) * 4;
  float a[4][4] = {};
  for (int k = 0; k < 64; k++) {
    float u[4], v[4];
#pragma unroll
    for (int r = 0; r < 4; r++) u[r] = Vs[(i0 + r) * 65 + k];
#pragma unroll
    for (int c = 0; c < 4; c++) v[c] = Vs[(j0 + c) * 65 + k] * fl[k];
#pragma unroll
    for (int r = 0; r < 4; r++)
#pragma unroll
      for (int c = 0; c < 4; c++) a[r][c] += u[r] * v[c];
  }
  float* dst = g_B + (size_t)m * 4096;
#pragma unroll
  for (int r = 0; r < 4; r++)
#pragma unroll
    for (int c = 0; c < 4; c++) dst[(i0 + r) * 64 + j0 + c] = a[r][c];
}

__global__ void k_recon_exp(int ns, float* __restrict__ out) {  // state = V exp(w) V^T
  __shared__ float Vs[4160], fe[64];
  const int m = blockIdx.x, t = threadIdx.x;
  loadV(g_Vt + (size_t)m * 4096, Vs, t);
  if (t < 64) fe[t] = expf(g_w[(size_t)m * 64 + t]);
  __syncthreads();
  const int i0 = (t >> 4) * 4, j0 = (t & 15) * 4;
  float a[4][4] = {};
  for (int k = 0; k < 64; k++) {
    float u[4], v[4];
#pragma unroll
    for (int r = 0; r < 4; r++) u[r] = Vs[(i0 + r) * 65 + k];
#pragma unroll
    for (int c = 0; c < 4; c++) v[c] = Vs[(j0 + c) * 65 + k] * fe[k];
#pragma unroll
    for (int r = 0; r < 4; r++)
#pragma unroll
      for (int c = 0; c < 4; c++) a[r][c] += u[r] * v[c];
  }
  float* st = g_state + (size_t)(ns * 512 + m) * 4096;
  int b = m >> 4, c0 = m & 15;
  float* od = out + (size_t)((b * 48 + (ns - 2) * 16 + c0)) * 4096;
#pragma unroll
  for (int r = 0; r < 4; r++)
#pragma unroll
    for (int c = 0; c < 4; c++) {
      float v = a[r][c];
      st[(i0 + r) * 64 + j0 + c] = v;
      od[(i0 + r) * 64 + j0 + c] = v;
    }
}

// ---------------- mean of weighted logs --------------------------------------
__global__ void k_mean(const float* __restrict__ wts, int o, int J, int ns) {
  const int bc = blockIdx.x, t = threadIdx.x;
  float wl[4][4];
  for (int j = 0; j < J; j++)
    for (int k = 0; k < 4; k++) wl[j][k] = wts[(o + j) * 4 + k];
  const float inv = 1.f / (float)J;
  float* dst = g_Lstate + (size_t)(ns * 512 + bc) * 4096;
  for (int e = t; e < 4096; e += 256) {
    float acc = 0.f;
    for (int j = 0; j < J; j++) {
      acc += wl[j][0] * g_Lstate[(size_t)(j * 512 + bc) * 4096 + e];
      for (int r = 0; r < 3; r++)
        acc += wl[j][r + 1] * g_B[(size_t)((j * 3 + r) * 512 + bc) * 4096 + e];
    }
    dst[e] = acc * inv;
  }
}

// ---------------- host ---------------------------------------------------------
extern "C" void kernel_launch(void* const* d_in, const int* in_sizes, int n_in,
                              void* d_out, int out_size) {
  const float* s0  = (const float*)d_in[0];
  const float* s1  = (const float*)d_in[1];
  const float* wts = (const float*)d_in[2];
  const float* Wp0 = (const float*)d_in[3];
  const float* Wp1 = (const float*)d_in[4];
  const float* Wop = (const float*)d_in[5];
  float* out = (float*)d_out;
  (void)in_sizes; (void)n_in; (void)out_size;

  // preprocess: reig(bimap(s_i, Wp_i)) + cached log
  k_bimap_pre<<<1024, 256>>>(s0, s1, Wp0, Wp1);
  k_eigh<<<1024, 128>>>(0, 0);
  k_recon_pre<<<1024, 256>>>();

  const int offs[3] = {0, 2, 5};
  for (int s = 0; s < 3; s++) {
    int J = 2 + s, o = offs[s], ns = 2 + s;
    int nb = J * 3 * 512;
    k_bimap_step<<<nb, 256>>>(Wop, o);
    k_eigh<<<nb, 128>>>(0, 0);
    k_recon_log<<<nb, 256>>>();
    k_mean<<<512, 256>>>(wts, o, J, ns);
    k_eigh<<<512, 128>>>(1, ns * 512);
    k_recon_exp<<<512, 256>>>(ns, out);
  }
}

// round 16
// speedup vs baseline: 1.0253x; 1.0253x over previous
#include <cuda_runtime.h>
#include <math.h>

#define EPSV 1e-4f

// scratch (device globals; allocation is banned)
__device__ __align__(16) float g_B[25165824];       // 12*512 matrices of 64x64
__device__ __align__(16) float g_state[10485760];   // 5*512*4096
__device__ __align__(16) float g_Lstate[10485760];  // logm(states)

// ---------------- bimap: Y = W X W^T (64x64) --------------------------------
__device__ __forceinline__ void bimap64(const float* __restrict__ X,
                                        const float* __restrict__ W,
                                        float* __restrict__ Y,
                                        float* Ws, float* Xs) {
  const int t = threadIdx.x;
  for (int i = t; i < 4096; i += 256) {
    int r = i >> 6, c = i & 63;
    Ws[r * 65 + c] = W[i];
    Xs[r * 65 + c] = X[i];
  }
  __syncthreads();
  const int i0 = (t >> 4) * 4, j0 = (t & 15) * 4;
  float acc[4][4] = {};
  for (int k = 0; k < 64; k++) {          // T = W * X
    float a[4], b[4];
#pragma unroll
    for (int r = 0; r < 4; r++) a[r] = Ws[(i0 + r) * 65 + k];
#pragma unroll
    for (int c = 0; c < 4; c++) b[c] = Xs[k * 65 + j0 + c];
#pragma unroll
    for (int r = 0; r < 4; r++)
#pragma unroll
      for (int c = 0; c < 4; c++) acc[r][c] += a[r] * b[c];
  }
  __syncthreads();
#pragma unroll
  for (int r = 0; r < 4; r++)
#pragma unroll
    for (int c = 0; c < 4; c++) Xs[(i0 + r) * 65 + j0 + c] = acc[r][c];
  __syncthreads();
  float acc2[4][4] = {};
  for (int k = 0; k < 64; k++) {          // Y = T * W^T
    float a[4], b[4];
#pragma unroll
    for (int r = 0; r < 4; r++) a[r] = Xs[(i0 + r) * 65 + k];
#pragma unroll
    for (int c = 0; c < 4; c++) b[c] = Ws[(j0 + c) * 65 + k];
#pragma unroll
    for (int r = 0; r < 4; r++)
#pragma unroll
      for (int c = 0; c < 4; c++) acc2[r][c] += a[r] * b[c];
  }
#pragma unroll
  for (int r = 0; r < 4; r++)
#pragma unroll
    for (int c = 0; c < 4; c++) Y[(i0 + r) * 64 + j0 + c] = acc2[r][c];
}

__global__ void k_bimap_pre(const float* __restrict__ s0, const float* __restrict__ s1,
                            const float* __restrict__ Wp0, const float* __restrict__ Wp1) {
  __shared__ float Ws[4160], Xs[4160];
  int m = blockIdx.x, slot = m >> 9, bc = m & 511;
  const float* X = (slot ? s1 : s0) + (size_t)bc * 4096;
  const float* W = slot ? Wp1 : Wp0;
  bimap64(X, W, g_B + (size_t)m * 4096, Ws, Xs);
}

__global__ void k_bimap_step(const float* __restrict__ Wop, int o) {
  __shared__ float Ws[4160], Xs[4160];
  int m = blockIdx.x;
  int j = m / 1536, rem = m % 1536, r = rem / 512, k = r + 1, bc = rem % 512;
  const float* X = g_state + (size_t)(j * 512 + bc) * 4096;
  const float* W = Wop + (size_t)((o + j) * 4 + k) * 4096;
  bimap64(X, W, g_B + (size_t)m * 4096, Ws, Xs);
}

// ---------------- batched Jacobi eigh + fused spectral reconstruction --------
// mode 0: src g_B[m]       -> state = V clip V^T ; Lstate = V log(clip) V^T
// mode 1: src g_B[m]       -> g_B[m] = V log(clip) V^T   (in-place)
// mode 2: src g_Lstate[off+m] -> state[ns] = V exp V^T ; also to d_out
__global__ void __launch_bounds__(128, 8) k_eigh(int mode, int off, int ns,
                                                 float* __restrict__ out) {
  __shared__ float As[4160];
  __shared__ __align__(16) float Vt[4096];   // column-major V[col*64+row]
  __shared__ float red[4];
  __shared__ float fva[64], fvb[64];
  const int t = threadIdx.x;
  const int lane = t & 31, wid = t >> 5;   // wid 0..3
  const int m = blockIdx.x;
  const float* src = (mode == 2) ? (g_Lstate + (size_t)(off + m) * 4096)
                                 : (g_B + (size_t)m * 4096);
  float2* V2 = reinterpret_cast<float2*>(Vt);

  float loc = 0.f;
  for (int i = t; i < 4096; i += 128) {
    int r = i >> 6, c = i & 63;
    float v = 0.5f * (src[i] + src[c * 64 + r]);
    As[r * 65 + c] = v;
    Vt[i] = (r == c) ? 1.f : 0.f;   // col-major identity (same diagonal set)
    loc += v * v;
  }
#pragma unroll
  for (int o2 = 16; o2; o2 >>= 1) loc += __shfl_xor_sync(~0u, loc, o2);
  if (lane == 0) red[wid] = loc;
  __syncthreads();
  const float thr = (red[0] + red[1] + red[2] + red[3]) * 3e-11f;

  for (int sweep = 0; sweep < 18; sweep++) {
    // convergence check: off-diagonal Frobenius^2 (all threads same decision)
    float l2 = 0.f;
    for (int i = t; i < 4096; i += 128) {
      int r = i >> 6, c = i & 63;
      float v = As[r * 65 + c];
      l2 += (r != c) ? v * v : 0.f;
    }
#pragma unroll
    for (int o2 = 16; o2; o2 >>= 1) l2 += __shfl_xor_sync(~0u, l2, o2);
    __syncthreads();                 // WAR guard (warps may drift in trivial rounds)
    if (lane == 0) red[wid] = l2;
    __syncthreads();
    const float sumoff = red[0] + red[1] + red[2] + red[3];
    if (sumoff <= thr) break;
    // adaptive per-pair trivial threshold: skipped mass <= 1% of current off^2
    const float skipthr = fmaxf(thr, sumoff * 0.01f) * (1.f / 2016.f);

    for (int mr = 1; mr < 64; mr++) {
      const int h = 31 - __clz(mr);
      const int msk = (1 << h) - 1;
      // phase a: every warp computes all 32 rotations (lane = pair index)
      const int pi = ((lane >> h) << (h + 1)) | (lane & msk);
      const int qi = pi ^ mr;
      float app = As[pi * 65 + pi];
      float aqq = As[qi * 65 + qi];
      float apq = As[pi * 65 + qi];
      float cc = 1.f, ss = 0.f;
      if (apq * apq > skipthr) {
        float tau = (aqq - app) / (2.f * apq);
        float tt = copysignf(1.f, tau) / (fabsf(tau) + sqrtf(1.f + tau * tau));
        cc = rsqrtf(1.f + tt * tt);
        ss = tt * cc;
      }
      // block-uniform triviality (every warp computes the identical set)
      if (__all_sync(~0u, ss == 0.f)) continue;  // no writes -> no barriers needed
      __syncthreads();  // rotation reads done before block writes

      // phase b: fused two-sided update. Thread (wid,lane) owns A blocks
      // (i=lane, j=wid+4k, k<8) and V rows {2*lane, 2*lane+1} for col-pairs j.
#pragma unroll
      for (int k = 0; k < 8; k++) {
        const int j = wid + 4 * k;
        const float cj = __shfl_sync(~0u, cc, j);
        const float sj = __shfl_sync(~0u, ss, j);
        const int tj = (sj == 0.f);                  // warp-uniform
        const int pj = ((j >> h) << (h + 1)) | (j & msk);
        const int qj = pj ^ mr;

        float b00 = As[pi * 65 + pj], b01 = As[pi * 65 + qj];
        float b10 = As[qi * 65 + pj], b11 = As[qi * 65 + qj];
        float t00 = cc * b00 - ss * b10, t01 = cc * b01 - ss * b11;
        float t10 = ss * b00 + cc * b10, t11 = ss * b01 + cc * b11;
        As[pi * 65 + pj] = t00 * cj - t01 * sj;
        As[pi * 65 + qj] = t00 * sj + t01 * cj;
        As[qi * 65 + pj] = t10 * cj - t11 * sj;
        As[qi * 65 + qj] = t10 * sj + t11 * cj;

        if (!tj) {
          float2 vp = V2[pj * 32 + lane], vq = V2[qj * 32 + lane];
          float2 np, nq;
          np.x = cj * vp.x - sj * vq.x;  np.y = cj * vp.y - sj * vq.y;
          nq.x = sj * vp.x + cj * vq.x;  nq.y = sj * vp.y + cj * vq.y;
          V2[pj * 32 + lane] = np;
          V2[qj * 32 + lane] = nq;
        }
      }
      __syncthreads();
    }
  }

  // ---- fused reconstruction epilogue: C = V f(w) V^T from smem V ----
  if (t < 64) {
    float w = As[t * 65 + t];
    if (mode == 2) {
      fva[t] = expf(w);
    } else {
      float cw = fmaxf(w, EPSV);
      fva[t] = (mode == 0) ? cw : logf(cw);
      fvb[t] = logf(cw);
    }
  }
  __syncthreads();

  if (mode == 0) {
    const int slot = m >> 9, bc = m & 511;
    float* st = g_state + (size_t)(slot * 512 + bc) * 4096;
    float* ls = g_Lstate + (size_t)(slot * 512 + bc) * 4096;
    for (int t2 = 0; t2 < 2; t2++) {
      const int tid = t + 128 * t2;
      const int i0 = (tid >> 4) * 4, j0 = (tid & 15) * 4;
      float a[4][4] = {}, b[4][4] = {};
      for (int k = 0; k < 64; k++) {
        float u[4], v[4];
#pragma unroll
        for (int r = 0; r < 4; r++) u[r] = Vt[k * 64 + i0 + r];
#pragma unroll
        for (int c = 0; c < 4; c++) v[c] = Vt[k * 64 + j0 + c];
        float fa = fva[k], fb = fvb[k];
#pragma unroll
        for (int r = 0; r < 4; r++)
#pragma unroll
          for (int c = 0; c < 4; c++) {
            float p = u[r] * v[c];
            a[r][c] += p * fa;
            b[r][c] += p * fb;
          }
      }
#pragma unroll
      for (int r = 0; r < 4; r++)
#pragma unroll
        for (int c = 0; c < 4; c++) {
          st[(i0 + r) * 64 + j0 + c] = a[r][c];
          ls[(i0 + r) * 64 + j0 + c] = b[r][c];
        }
    }
  } else {
    float* d0 = (mode == 1) ? (g_B + (size_t)m * 4096)
                            : (g_state + (size_t)(ns * 512 + m) * 4096);
    float* d1 = nullptr;
    if (mode == 2) {
      int b = m >> 4, c0 = m & 15;
      d1 = out + (size_t)(b * 48 + (ns - 2) * 16 + c0) * 4096;
    }
    for (int t2 = 0; t2 < 2; t2++) {
      const int tid = t + 128 * t2;
      const int i0 = (tid >> 4) * 4, j0 = (tid & 15) * 4;
      float a[4][4] = {};
      for (int k = 0; k < 64; k++) {
        float u[4], v[4];
        float fa = fva[k];
#pragma unroll
        for (int r = 0; r < 4; r++) u[r] = Vt[k * 64 + i0 + r];
#pragma unroll
        for (int c = 0; c < 4; c++) v[c] = Vt[k * 64 + j0 + c] * fa;
#pragma unroll
        for (int r = 0; r < 4; r++)
#pragma unroll
          for (int c = 0; c < 4; c++) a[r][c] += u[r] * v[c];
      }
#pragma unroll
      for (int r = 0; r < 4; r++)
#pragma unroll
        for (int c = 0; c < 4; c++) {
          float v = a[r][c];
          d0[(i0 + r) * 64 + j0 + c] = v;
          if (mode == 2) d1[(i0 + r) * 64 + j0 + c] = v;
        }
    }
  }
}

// ---------------- mean of weighted logs --------------------------------------
__global__ void k_mean(const float* __restrict__ wts, int o, int J, int ns) {
  const int bc = blockIdx.x, t = threadIdx.x;
  float wl[4][4];
  for (int j = 0; j < J; j++)
    for (int k = 0; k < 4; k++) wl[j][k] = wts[(o + j) * 4 + k];
  const float inv = 1.f / (float)J;
  float* dst = g_Lstate + (size_t)(ns * 512 + bc) * 4096;
  for (int e = t; e < 4096; e += 256) {
    float acc = 0.f;
    for (int j = 0; j < J; j++) {
      acc += wl[j][0] * g_Lstate[(size_t)(j * 512 + bc) * 4096 + e];
      for (int r = 0; r < 3; r++)
        acc += wl[j][r + 1] * g_B[(size_t)((j * 3 + r) * 512 + bc) * 4096 + e];
    }
    dst[e] = acc * inv;
  }
}

// ---------------- host ---------------------------------------------------------
extern "C" void kernel_launch(void* const* d_in, const int* in_sizes, int n_in,
                              void* d_out, int out_size) {
  const float* s0  = (const float*)d_in[0];
  const float* s1  = (const float*)d_in[1];
  const float* wts = (const float*)d_in[2];
  const float* Wp0 = (const float*)d_in[3];
  const float* Wp1 = (const float*)d_in[4];
  const float* Wop = (const float*)d_in[5];
  float* out = (float*)d_out;
  (void)in_sizes; (void)n_in; (void)out_size;

  // preprocess: reig(bimap(s_i, Wp_i)) with fused state+log reconstruction
  k_bimap_pre<<<1024, 256>>>(s0, s1, Wp0, Wp1);
  k_eigh<<<1024, 128>>>(0, 0, 0, nullptr);

  const int offs[3] = {0, 2, 5};
  for (int s = 0; s < 3; s++) {
    int J = 2 + s, o = offs[s], ns = 2 + s;
    int nb = J * 3 * 512;
    k_bimap_step<<<nb, 256>>>(Wop, o);
    k_eigh<<<nb, 128>>>(1, 0, 0, nullptr);
    k_mean<<<512, 256>>>(wts, o, J, ns);
    k_eigh<<<512, 128>>>(2, ns * 512, ns, out);
  }
}